// round 13
// baseline (speedup 1.0000x reference)
#include <cuda_runtime.h>
#include <cuda_bf16.h>
#include <math.h>
#include <stdint.h>

// ---------------------------------------------------------------------------
// Problem constants (Gemma2 decoder layer)
// ---------------------------------------------------------------------------
#define S_LEN   2048
#define H_DIM   3584
#define NH      16
#define NKV     8
#define HD      256
#define NQD     (NH * HD)         // 4096
#define NKVD    (NKV * HD)        // 2048
#define QKVD    (NQD + 2 * NKVD)  // 8192
#define I_DIM   14336
#define GUD     (2 * I_DIM)       // 28672
#define SCALE_F 0.0625f
#define SOFTCAP 50.0f
#define EPS_F   1e-6f

typedef __nv_bfloat16 bf16;

// ---------------------------------------------------------------------------
// Tiled operand layout: matrix [R, K] (bf16 hi/lo) stored as 16KB tiles.
// tile (rt = r/128, kt = k/32), ktn = K/32 tiles per row-band.
// tile bytes: [hi: h0 4KB | h1 4KB | lo: h0 4KB | h1 4KB], h = k16 half.
// ---------------------------------------------------------------------------
__device__ __forceinline__ size_t tile_off(int r, int k, int ktn) {
    size_t t = (size_t)(r >> 7) * ktn + (k >> 5);
    int rr = r & 127, cc = k & 31;
    return t * 16384 + (size_t)((cc >> 4) * 4096 + rr * 32
         + ((((cc >> 3) & 1) ^ ((rr >> 2) & 1)) << 4) + (cc & 7) * 2);
}

// ---------------------------------------------------------------------------
// Device scratch (static; runtime allocation is forbidden)
// ---------------------------------------------------------------------------
__device__ float g_qkv [(size_t)S_LEN * QKVD];
__device__ float g_sc  [(size_t)NH * S_LEN * S_LEN];
__device__ float g_tmp [(size_t)S_LEN * H_DIM];
__device__ float g_x1  [(size_t)S_LEN * H_DIM];
__device__ float g_gu  [(size_t)S_LEN * GUD];

#define TBUF(name, R, K) __device__ __align__(16384) char name[(size_t)(R) * (K) * 4]
TBUF(c_wqkvt, QKVD, H_DIM);
TBUF(c_wot,  H_DIM, NQD);
TBUF(c_wgut, GUD,  H_DIM);
TBUF(c_wdt,  H_DIM, I_DIM);
TBUF(c_h,    S_LEN, H_DIM);
TBUF(c_q,    S_LEN, NQD);
TBUF(c_k,    S_LEN, NKVD);
TBUF(c_vt,   NKVD, S_LEN);
TBUF(c_p,    (size_t)NH * S_LEN, S_LEN);
TBUF(c_at,   S_LEN, NQD);
TBUF(c_gu,   S_LEN, I_DIM);

// ---------------------------------------------------------------------------
// helpers
// ---------------------------------------------------------------------------
__device__ __forceinline__ void bsplit(float x, bf16& h, bf16& l) {
    h = __float2bfloat16_rn(x);
    l = __float2bfloat16_rn(x - __bfloat162float(h));
}
__device__ __forceinline__ uint32_t packbf(bf16 a, bf16 b) {
    __nv_bfloat162 t(a, b);
    return *reinterpret_cast<uint32_t*>(&t);
}

template<bool IS_MAX>
__device__ __forceinline__ float block_reduce(float v) {
    __shared__ float sh[8];
    __syncthreads();
    int lane = threadIdx.x & 31, wid = threadIdx.x >> 5;
    #pragma unroll
    for (int o = 16; o; o >>= 1) {
        float t = __shfl_xor_sync(0xffffffffu, v, o);
        v = IS_MAX ? fmaxf(v, t) : (v + t);
    }
    if (lane == 0) sh[wid] = v;
    __syncthreads();
    if (wid == 0) {
        float r = (threadIdx.x < 8) ? sh[threadIdx.x] : (IS_MAX ? -3.4e38f : 0.0f);
        #pragma unroll
        for (int o = 4; o; o >>= 1) {
            float t = __shfl_xor_sync(0xffffffffu, r, o);
            r = IS_MAX ? fmaxf(r, t) : (r + t);
        }
        if (lane == 0) sh[0] = r;
    }
    __syncthreads();
    return sh[0];
}

__device__ __forceinline__ uint32_t smem_u32(const void* p) {
    uint32_t a;
    asm("{ .reg .u64 t; cvta.to.shared.u64 t, %1; cvt.u32.u64 %0, t; }" : "=r"(a) : "l"(p));
    return a;
}

#define MBAR_INIT(a, cnt) asm volatile("mbarrier.init.shared.b64 [%0], %1;" :: "r"(a), "r"(cnt) : "memory")
#define MBAR_EXPECT_TX(a, n) asm volatile("mbarrier.arrive.expect_tx.shared.b64 _, [%0], %1;" :: "r"(a), "r"(n) : "memory")
#define MBAR_WAIT(a, ph)  do {                                                               \
    asm volatile("{\n .reg .pred P1;\n"                                                      \
                 "WL%=:\n mbarrier.try_wait.parity.acquire.cta.shared::cta.b64 P1,[%0],%1,0x989680;\n" \
                 "@P1 bra.uni WD%=;\n bra.uni WL%=;\nWD%=:\n}"                               \
                 :: "r"(a), "r"(ph) : "memory"); } while (0)
#define BULK_G2S(dst, src, n, bar) \
    asm volatile("cp.async.bulk.shared::cluster.global.mbarrier::complete_tx::bytes [%0], [%1], %2, [%3];" \
                 :: "r"(dst), "l"(__cvta_generic_to_global(src)), "r"(n), "r"(bar) : "memory")

__device__ __forceinline__ void mma_bf16(float* c, const uint32_t* a, const uint32_t* b) {
    asm volatile(
        "mma.sync.aligned.m16n8k16.row.col.f32.bf16.bf16.f32 "
        "{%0,%1,%2,%3}, {%4,%5,%6,%7}, {%8,%9}, {%0,%1,%2,%3};\n"
        : "+f"(c[0]), "+f"(c[1]), "+f"(c[2]), "+f"(c[3])
        : "r"(a[0]), "r"(a[1]), "r"(a[2]), "r"(a[3]), "r"(b[0]), "r"(b[1]));
}
__device__ __forceinline__ void ldsm4(uint32_t* r, uint32_t addr) {
    asm volatile("ldmatrix.sync.aligned.m8n8.x4.shared.b16 {%0,%1,%2,%3}, [%4];"
                 : "=r"(r[0]), "=r"(r[1]), "=r"(r[2]), "=r"(r[3]) : "r"(addr));
}

// ---------------------------------------------------------------------------
// mma.sync GEMM on pre-tiled operands:  C[M, N] = A[M, K] * B[N, K]^T
//   CTA tile 128x256x32, 8 warps (2M x 4N) of 64x64, split-bf16 3-product.
//   Stage feed = 3 cp.async.bulk (A tile + 2 B tiles = 48KB) + mbarrier tx.
//   4-stage ring. CMODE 0 plain; 1 causal skip; 2 K clip (brow*4+4 tiles).
//   OUT 0: fp32 row-major (+ bz*sC). OUT 1: tiled bf16 hi/lo (ldcT ktn).
// ---------------------------------------------------------------------------
#define STG_BYTES 49152
#define NSTG      4
#define GEMM_SMEM (1024 + NSTG * STG_BYTES)

template<int CMODE, int OUT>
__global__ void __launch_bounds__(256, 1)
gemm_mma(const char* __restrict__ At, const char* __restrict__ Bt,
         float* __restrict__ C, char* __restrict__ Ct,
         int nkTot, int ldaT, int ldbT, int ldcF, int ldcT, long long sC,
         long long sAT, long long sBT, int zdivB, int ccol)
{
    const int brow = blockIdx.x, bcol = blockIdx.y, bz = blockIdx.z;
    if (CMODE == 1 && 2 * bcol > brow) return;

    int nk = nkTot;
    if (CMODE == 2) nk = min(nkTot, brow * 4 + 4);

    const long long aBase = bz * sAT + (long long)brow * ldaT;
    const long long bT0 = (bz / zdivB) * sBT + (long long)(bcol * 2) * ldbT;
    const long long bT1 = bT0 + ldbT;

    extern __shared__ char smem[];
    const uint32_t smb = smem_u32(smem);

    const int tid  = threadIdx.x;
    const int lane = tid & 31;
    const int wid  = tid >> 5;
    const int warp_m = (wid & 1) * 64;
    const int warp_n = (wid >> 1) * 64;
    const uint32_t bbadd = 16384u + (uint32_t)(warp_n >> 7) * 16384u;

    if (tid == 0) {
        #pragma unroll
        for (int s = 0; s < NSTG; s++) MBAR_INIT(smb + 16 * s, 1);
    }
    asm volatile("fence.proxy.async.shared::cta;" ::: "memory");
    __syncthreads();

    // ---- fragment smem offsets (within a 4KB k16 plane) ----
    const int bsel = lane >> 3, jj = lane & 7;
    uint32_t aoff[4], boff[2][2];
    #pragma unroll
    for (int mi = 0; mi < 4; mi++) {
        const int r = warp_m + mi * 16 + (bsel & 1) * 8 + jj;
        const int c = bsel >> 1;
        aoff[mi] = r * 32 + ((c ^ ((r >> 2) & 1)) << 4);
    }
    #pragma unroll
    for (int ng = 0; ng < 2; ng++)
        #pragma unroll
        for (int q = 0; q < 2; q++) {
            const int r = (warp_n & 127) + ng * 32 + q * 16 + (bsel >> 1) * 8 + jj;
            const int c = bsel & 1;
            boff[ng][q] = r * 32 + ((c ^ ((r >> 2) & 1)) << 4);
        }

    auto fill = [&](int kt, int s) {   // thread 0 only
        const uint32_t bar = smb + 16 * s;
        const uint32_t sb = smb + 1024 + s * STG_BYTES;
        MBAR_EXPECT_TX(bar, (uint32_t)STG_BYTES);
        BULK_G2S(sb,          At + (aBase + kt) * 16384LL, 16384u, bar);
        BULK_G2S(sb + 16384u, Bt + (bT0 + kt) * 16384LL,   16384u, bar);
        BULK_G2S(sb + 32768u, Bt + (bT1 + kt) * 16384LL,   16384u, bar);
    };

    float acc[4][8][4];
    #pragma unroll
    for (int mi = 0; mi < 4; mi++)
        #pragma unroll
        for (int ni = 0; ni < 8; ni++)
            #pragma unroll
            for (int r = 0; r < 4; r++) acc[mi][ni][r] = 0.0f;

    auto compute_stage = [&](int s) {
        const uint32_t sb = smb + 1024 + s * STG_BYTES;
        #pragma unroll
        for (int h = 0; h < 2; h++) {
            const uint32_t aph = sb + h * 4096u;
            const uint32_t apl = aph + 8192u;
            const uint32_t bph = sb + bbadd + h * 4096u;
            const uint32_t bpl = bph + 8192u;

            uint32_t ah[4][4], al[4][4];
            #pragma unroll
            for (int mi = 0; mi < 4; mi++) {
                ldsm4(ah[mi], aph + aoff[mi]);
                ldsm4(al[mi], apl + aoff[mi]);
            }
            #pragma unroll
            for (int ng = 0; ng < 2; ng++) {
                uint32_t bh[4][2], bl[4][2];
                #pragma unroll
                for (int q = 0; q < 2; q++) {
                    uint32_t r[4];
                    ldsm4(r, bph + boff[ng][q]);
                    bh[2*q][0] = r[0]; bh[2*q][1] = r[1];
                    bh[2*q+1][0] = r[2]; bh[2*q+1][1] = r[3];
                    ldsm4(r, bpl + boff[ng][q]);
                    bl[2*q][0] = r[0]; bl[2*q][1] = r[1];
                    bl[2*q+1][0] = r[2]; bl[2*q+1][1] = r[3];
                }
                #pragma unroll
                for (int ni = 0; ni < 4; ni++)
                    #pragma unroll
                    for (int mi = 0; mi < 4; mi++)
                        mma_bf16(acc[mi][ng*4+ni], ah[mi], bh[ni]);
                #pragma unroll
                for (int ni = 0; ni < 4; ni++)
                    #pragma unroll
                    for (int mi = 0; mi < 4; mi++)
                        mma_bf16(acc[mi][ng*4+ni], al[mi], bh[ni]);
                #pragma unroll
                for (int ni = 0; ni < 4; ni++)
                    #pragma unroll
                    for (int mi = 0; mi < 4; mi++)
                        mma_bf16(acc[mi][ng*4+ni], ah[mi], bl[ni]);
            }
        }
    };

    if (tid == 0) {
        for (int s = 0; s < NSTG && s < nk; s++) fill(s, s);
    }
    for (int kt = 0; kt < nk; kt++) {
        const int s = kt & (NSTG - 1);
        const int m = kt >> 2;
        MBAR_WAIT(smb + 16 * s, m & 1);
        compute_stage(s);
        __syncthreads();
        if (tid == 0 && kt + NSTG < nk) fill(kt + NSTG, s);
    }

    // ---- epilogue ----
    const int fr = lane >> 2, fc = (lane & 3) * 2;
    #pragma unroll
    for (int mi = 0; mi < 4; mi++) {
        const int row = brow * 128 + warp_m + mi * 16 + fr;
        #pragma unroll
        for (int ni = 0; ni < 8; ni++) {
            const int col = bcol * 256 + bz * ccol + warp_n + ni * 8 + fc;
            if (OUT == 0) {
                float* c0 = C + bz * sC + (long long)row * ldcF + col;
                float* c1 = C + bz * sC + (long long)(row + 8) * ldcF + col;
                *(float2*)c0 = make_float2(acc[mi][ni][0], acc[mi][ni][1]);
                *(float2*)c1 = make_float2(acc[mi][ni][2], acc[mi][ni][3]);
            } else {
                bf16 h0,l0,h1,l1,h2,l2,h3,l3;
                bsplit(acc[mi][ni][0], h0, l0); bsplit(acc[mi][ni][1], h1, l1);
                bsplit(acc[mi][ni][2], h2, l2); bsplit(acc[mi][ni][3], h3, l3);
                size_t o0 = tile_off(row, col, ldcT);
                size_t o1 = tile_off(row + 8, col, ldcT);
                *(uint32_t*)(Ct + o0)        = packbf(h0, h1);
                *(uint32_t*)(Ct + o0 + 8192) = packbf(l0, l1);
                *(uint32_t*)(Ct + o1)        = packbf(h2, h3);
                *(uint32_t*)(Ct + o1 + 8192) = packbf(l2, l3);
            }
        }
    }
}

// ---------------------------------------------------------------------------
// Transpose + split + tile:  W[Kd, Nd] fp32 (row stride ldw) -> tiled T[Nd, Kd]
// ---------------------------------------------------------------------------
__global__ void tsplit_kernel(const float* __restrict__ W, char* __restrict__ T,
                              int Kd, int Nd, int ldw)
{
    __shared__ float t[32][33];
    const int n0 = blockIdx.x * 32, k0 = blockIdx.y * 32;
    const int tx = threadIdx.x, ty = threadIdx.y;
    const int ktn = Kd >> 5;
    #pragma unroll
    for (int i = 0; i < 4; i++)
        t[ty + i * 8][tx] = W[(long long)(k0 + ty + i * 8) * ldw + n0 + tx];
    __syncthreads();
    const int tid = ty * 32 + tx;
    if (tid < 128) {
        const int nn = tid >> 2, kq = (tid & 3) * 8;
        bf16 h[8], l[8];
        #pragma unroll
        for (int i = 0; i < 8; i++) bsplit(t[kq + i][nn], h[i], l[i]);
        const size_t off = tile_off(n0 + nn, k0 + kq, ktn);
        *(uint4*)(T + off) = make_uint4(packbf(h[0],h[1]), packbf(h[2],h[3]),
                                        packbf(h[4],h[5]), packbf(h[6],h[7]));
        *(uint4*)(T + off + 8192) = make_uint4(packbf(l[0],l[1]), packbf(l[2],l[3]),
                                               packbf(l[4],l[5]), packbf(l[6],l[7]));
    }
}

// ---------------------------------------------------------------------------
// RMSNorm -> tiled hi/lo
// ---------------------------------------------------------------------------
__global__ void rmsnorm_split_kernel(const float* __restrict__ x,
                                     const float* __restrict__ w,
                                     char* __restrict__ out)
{
    const int row = blockIdx.x;
    const size_t base = (size_t)row * H_DIM;
    float ss = 0.0f;
    for (int j = threadIdx.x; j < H_DIM; j += blockDim.x) {
        float v = x[base + j]; ss += v * v;
    }
    ss = block_reduce<false>(ss);
    const float inv = rsqrtf(ss / (float)H_DIM + EPS_F);
    for (int ch = threadIdx.x; ch < H_DIM / 8; ch += blockDim.x) {
        const int k0 = ch * 8;
        const float4 a = *(const float4*)(x + base + k0);
        const float4 b = *(const float4*)(x + base + k0 + 4);
        const float4 wa = *(const float4*)(w + k0);
        const float4 wb = *(const float4*)(w + k0 + 4);
        const float vv[8] = { a.x*inv*wa.x, a.y*inv*wa.y, a.z*inv*wa.z, a.w*inv*wa.w,
                              b.x*inv*wb.x, b.y*inv*wb.y, b.z*inv*wb.z, b.w*inv*wb.w };
        bf16 h[8], l[8];
        #pragma unroll
        for (int i = 0; i < 8; i++) bsplit(vv[i], h[i], l[i]);
        const size_t off = tile_off(row, k0, H_DIM / 32);
        *(uint4*)(out + off) = make_uint4(packbf(h[0],h[1]), packbf(h[2],h[3]),
                                          packbf(h[4],h[5]), packbf(h[6],h[7]));
        *(uint4*)(out + off + 8192) = make_uint4(packbf(l[0],l[1]), packbf(l[2],l[3]),
                                                 packbf(l[4],l[5]), packbf(l[6],l[7]));
    }
}

__global__ void add_rmsnorm_kernel(const float* __restrict__ resid,
                                   const float* __restrict__ t,
                                   const float* __restrict__ w,
                                   float* __restrict__ out)
{
    const size_t base = (size_t)blockIdx.x * H_DIM;
    float ss = 0.0f;
    for (int j = threadIdx.x; j < H_DIM; j += blockDim.x) {
        float v = t[base + j]; ss += v * v;
    }
    ss = block_reduce<false>(ss);
    const float inv = rsqrtf(ss / (float)H_DIM + EPS_F);
    for (int j = threadIdx.x; j < H_DIM; j += blockDim.x)
        out[base + j] = resid[base + j] + t[base + j] * inv * w[j];
}

// ---------------------------------------------------------------------------
// RoPE -> tiled Q (ktn=128) and K (ktn=64)
// ---------------------------------------------------------------------------
__global__ void rope_split_kernel(const float* __restrict__ qkv,
                                  char* __restrict__ qt, char* __restrict__ kt)
{
    const int p = blockIdx.x;
    const int total = (NH + NKV) * 128;
    for (int t = threadIdx.x; t < total; t += blockDim.x) {
        const int d = t & 127;
        const float inv = powf(10000.0f, -(float)d * (1.0f / 128.0f));
        float sn, cs; sincosf((float)p * inv, &sn, &cs);
        size_t sbase; int col; char* dst; int ktn;
        if (t < NH * 128) {
            const int head = t >> 7;
            sbase = (size_t)p * QKVD + head * HD + d;
            col = head * HD + d; dst = qt; ktn = NQD / 32;
        } else {
            const int head = (t - NH * 128) >> 7;
            sbase = (size_t)p * QKVD + NQD + head * HD + d;
            col = head * HD + d; dst = kt; ktn = NKVD / 32;
        }
        const float a = qkv[sbase], b = qkv[sbase + 128];
        bf16 h, l;
        size_t o = tile_off(p, col, ktn);
        bsplit(a * cs - b * sn, h, l);
        *(bf16*)(dst + o) = h; *(bf16*)(dst + o + 8192) = l;
        o = tile_off(p, col + 128, ktn);
        bsplit(b * cs + a * sn, h, l);
        *(bf16*)(dst + o) = h; *(bf16*)(dst + o + 8192) = l;
    }
}

// ---------------------------------------------------------------------------
// Softcap + causal softmax -> tiled P per head (ktn=64); tail zeroed
// ---------------------------------------------------------------------------
__global__ void softmax_split_kernel(float* __restrict__ sc, char* __restrict__ pt)
{
    const int i = blockIdx.x, h = blockIdx.y;
    const size_t base = ((size_t)h * S_LEN + i) * S_LEN;
    float* row = sc + base;
    char* ph = pt + (size_t)h * ((S_LEN / 128) * (S_LEN / 32) * 16384);
    const int n = i + 1;

    float sm = 0.0f;
    for (int j = threadIdx.x; j < n; j += blockDim.x) {
        const float e = __expf(row[j] * (SCALE_F * 2.0f / SOFTCAP));
        const float cap = SOFTCAP * (1.0f - __fdividef(2.0f, e + 1.0f));
        const float p = __expf(cap);
        row[j] = p;
        sm += p;
    }
    sm = block_reduce<false>(sm);
    const float invs = 1.0f / sm;

    for (int j = threadIdx.x; j < n; j += blockDim.x) {
        bf16 hh, ll; bsplit(row[j] * invs, hh, ll);
        const size_t o = tile_off(i, j, S_LEN / 32);
        *(bf16*)(ph + o) = hh; *(bf16*)(ph + o + 8192) = ll;
    }
    const bf16 z = __float2bfloat16(0.0f);
    for (int j = n + threadIdx.x; j < S_LEN; j += blockDim.x) {
        const size_t o = tile_off(i, j, S_LEN / 32);
        *(bf16*)(ph + o) = z; *(bf16*)(ph + o + 8192) = z;
    }
}

// ---------------------------------------------------------------------------
// gelu_tanh(gate) * up -> tiled hi/lo (ktn=448)
// ---------------------------------------------------------------------------
__global__ void gelumul_split_kernel(const float* __restrict__ gu, char* __restrict__ out)
{
    const int row = blockIdx.y;
    const int col = (blockIdx.x * blockDim.x + threadIdx.x) * 4;
    const float4 g4 = *(const float4*)(gu + (size_t)row * GUD + col);
    const float4 u4 = *(const float4*)(gu + (size_t)row * GUD + I_DIM + col);
    const float* gp = &g4.x; const float* up = &u4.x;
    bf16 h[4], l[4];
    #pragma unroll
    for (int t = 0; t < 4; t++) {
        const float xv = gp[t];
        const float inner = 0.7978845608028654f * (xv + 0.044715f * xv * xv * xv);
        const float r = 0.5f * xv * (1.0f + tanhf(inner)) * up[t];
        bsplit(r, h[t], l[t]);
    }
    const size_t off = tile_off(row, col, I_DIM / 32);
    *(uint2*)(out + off) = make_uint2(packbf(h[0], h[1]), packbf(h[2], h[3]));
    *(uint2*)(out + off + 8192) = make_uint2(packbf(l[0], l[1]), packbf(l[2], l[3]));
}

// ---------------------------------------------------------------------------
// Host launcher
// ---------------------------------------------------------------------------
#define SYM(v, s) do { cudaGetSymbolAddress((void**)&(v), s); } while (0)

extern "C" void kernel_launch(void* const* d_in, const int* in_sizes, int n_in,
                              void* d_out, int out_size)
{
    const float *x = nullptr, *w_in = nullptr, *w_pa = nullptr, *w_pf = nullptr,
                *w_pff = nullptr, *wq = nullptr, *wk = nullptr, *wv = nullptr,
                *wo = nullptr, *wg = nullptr, *wu = nullptr, *wd = nullptr;
    int c7 = 0, c14 = 0, c3584 = 0, c51 = 0;
    for (int i = 0; i < n_in; i++) {
        const int s = in_sizes[i];
        const float* p = (const float*)d_in[i];
        if (s == S_LEN * H_DIM) {
            if (c7 == 0) x = p; else if (c7 == 1) wk = p; else wv = p;
            c7++;
        } else if (s == H_DIM * NQD) {
            if (c14 == 0) wq = p; else wo = p;
            c14++;
        } else if (s == H_DIM) {
            if (c3584 == 0) w_in = p; else if (c3584 == 1) w_pa = p;
            else if (c3584 == 2) w_pf = p; else w_pff = p;
            c3584++;
        } else if (s == H_DIM * I_DIM) {
            if (c51 == 0) wg = p; else if (c51 == 1) wu = p; else wd = p;
            c51++;
        }
    }

    float *qkv_, *sc_, *tm_, *x1_, *gu_;
    SYM(qkv_, g_qkv); SYM(sc_, g_sc); SYM(tm_, g_tmp); SYM(x1_, g_x1); SYM(gu_, g_gu);
    char *wqkvt, *wot, *wgut, *wdt, *ht, *qt, *kt, *vt, *pt, *att, *gut;
    SYM(wqkvt, c_wqkvt); SYM(wot, c_wot); SYM(wgut, c_wgut); SYM(wdt, c_wdt);
    SYM(ht, c_h); SYM(qt, c_q); SYM(kt, c_k); SYM(vt, c_vt);
    SYM(pt, c_p); SYM(att, c_at); SYM(gut, c_gu);

    cudaFuncSetAttribute(gemm_mma<0,0>, cudaFuncAttributeMaxDynamicSharedMemorySize, GEMM_SMEM);
    cudaFuncSetAttribute(gemm_mma<1,0>, cudaFuncAttributeMaxDynamicSharedMemorySize, GEMM_SMEM);
    cudaFuncSetAttribute(gemm_mma<2,1>, cudaFuncAttributeMaxDynamicSharedMemorySize, GEMM_SMEM);

    const dim3 tb(32, 8);
    const long long SS = (long long)S_LEN * S_LEN;

    // ---- weight transpose + split + tile ----
    tsplit_kernel<<<dim3(NQD/32,  H_DIM/32), tb>>>(wq, wqkvt, H_DIM, NQD, NQD);
    tsplit_kernel<<<dim3(NKVD/32, H_DIM/32), tb>>>(wk, wqkvt + (size_t)(NQD>>7)*112*16384,
                                                   H_DIM, NKVD, NKVD);
    tsplit_kernel<<<dim3(NKVD/32, H_DIM/32), tb>>>(wv, wqkvt + (size_t)((NQD+NKVD)>>7)*112*16384,
                                                   H_DIM, NKVD, NKVD);
    tsplit_kernel<<<dim3(H_DIM/32, NQD/32),  tb>>>(wo, wot, NQD, H_DIM, H_DIM);
    tsplit_kernel<<<dim3(I_DIM/32, H_DIM/32), tb>>>(wg, wgut, H_DIM, I_DIM, I_DIM);
    tsplit_kernel<<<dim3(I_DIM/32, H_DIM/32), tb>>>(wu, wgut + (size_t)(I_DIM>>7)*112*16384,
                                                    H_DIM, I_DIM, I_DIM);
    tsplit_kernel<<<dim3(H_DIM/32, I_DIM/32), tb>>>(wd, wdt, I_DIM, H_DIM, H_DIM);

    // 1) pre-attn norm
    rmsnorm_split_kernel<<<S_LEN, 256>>>(x, w_in, ht);

    // 2) fused QKV projection
    gemm_mma<0,0><<<dim3(16, QKVD/256, 1), 256, GEMM_SMEM>>>(
        ht, wqkvt, qkv_, nullptr, 112, 112, 112, QKVD, 0, 0, 0, 0, 1, 0);

    // 3) RoPE; V transpose
    rope_split_kernel<<<S_LEN, 256>>>(qkv_, qt, kt);
    tsplit_kernel<<<dim3(NKVD/32, S_LEN/32), tb>>>(qkv_ + NQD + NKVD, vt,
                                                   S_LEN, NKVD, QKVD);

    // 4) scores = Q K^T per head (causal tile skip); kv head = z/2
    gemm_mma<1,0><<<dim3(16, S_LEN/256, NH), 256, GEMM_SMEM>>>(
        qt, kt, sc_, nullptr, 8, 128, 64, S_LEN, 0, SS, 8, 8, 2, 0);

    // 5) softcap + softmax -> tiled P
    softmax_split_kernel<<<dim3(S_LEN, NH), 256>>>(sc_, pt);

    // 6) attn = P @ V^T per head (K clipped; tiled output); kv head = z/2
    gemm_mma<2,1><<<dim3(16, 1, NH), 256, GEMM_SMEM>>>(
        pt, vt, nullptr, att, 64, 64, 64, 0, 128, 0, 1024, 128, 2, 256);

    // 7) output projection
    gemm_mma<0,0><<<dim3(16, H_DIM/256, 1), 256, GEMM_SMEM>>>(
        att, wot, tm_, nullptr, 128, 128, 128, H_DIM, 0, 0, 0, 0, 1, 0);

    // 8) x1 = x + rms_norm(attn_out)
    add_rmsnorm_kernel<<<S_LEN, 256>>>(x, tm_, w_pa, x1_);

    // 9) pre-FF norm
    rmsnorm_split_kernel<<<S_LEN, 256>>>(x1_, w_pf, ht);

    // 10) fused gate|up projection
    gemm_mma<0,0><<<dim3(16, GUD/256, 1), 256, GEMM_SMEM>>>(
        ht, wgut, gu_, nullptr, 112, 112, 112, GUD, 0, 0, 0, 0, 1, 0);

    // 11) gelu_tanh(gate) * up
    gelumul_split_kernel<<<dim3(I_DIM/(256*4), S_LEN), 256>>>(gu_, gut);

    // 12) down projection
    gemm_mma<0,0><<<dim3(16, H_DIM/256, 1), 256, GEMM_SMEM>>>(
        gut, wdt, tm_, nullptr, 448, 448, 448, H_DIM, 0, 0, 0, 0, 1, 0);

    // 13) out = x1 + rms_norm(ff_out)
    add_rmsnorm_kernel<<<S_LEN, 256>>>(x1_, tm_, w_pff, (float*)d_out);

    (void)n_in; (void)out_size;
}

// round 14
// speedup vs baseline: 1.3650x; 1.3650x over previous
#include <cuda_runtime.h>
#include <cuda_fp16.h>
#include <math.h>
#include <stdint.h>

// ---------------------------------------------------------------------------
// Problem constants (Gemma2 decoder layer)
// ---------------------------------------------------------------------------
#define S_LEN   2048
#define H_DIM   3584
#define NH      16
#define NKV     8
#define HD      256
#define NQD     (NH * HD)         // 4096
#define NKVD    (NKV * HD)        // 2048
#define QKVD    (NQD + 2 * NKVD)  // 8192
#define I_DIM   14336
#define GUD     (2 * I_DIM)       // 28672
#define SCALE_F 0.0625f
#define SOFTCAP 50.0f
#define EPS_F   1e-6f

// ---------------------------------------------------------------------------
// Tiled operand layouts (fp16).
// A-side tile (16KB, 128r x 32k): [hi: h0 4KB | h1 4KB | lo: h0 4KB | h1 4KB]
// B-side tile ( 8KB, 128r x 32k): [hi: h0 4KB | h1 4KB]   (no lo plane)
// element (r,k) offset within plane:
//   (cc>>4)*4096 + rr*32 + (((cc>>3)&1)^((rr>>2)&1))*16 + (cc&7)*2
// ---------------------------------------------------------------------------
__device__ __forceinline__ size_t plane_off(int rr, int cc) {
    return (size_t)((cc >> 4) * 4096 + rr * 32
         + ((((cc >> 3) & 1) ^ ((rr >> 2) & 1)) << 4) + (cc & 7) * 2);
}
__device__ __forceinline__ size_t tile_off(int r, int k, int ktn) {   // A-side
    size_t t = (size_t)(r >> 7) * ktn + (k >> 5);
    return t * 16384 + plane_off(r & 127, k & 31);
}
__device__ __forceinline__ size_t tile_off8(int r, int k, int ktn) {  // B-side
    size_t t = (size_t)(r >> 7) * ktn + (k >> 5);
    return t * 8192 + plane_off(r & 127, k & 31);
}

// ---------------------------------------------------------------------------
// Device scratch (static; runtime allocation is forbidden)
// ---------------------------------------------------------------------------
__device__ float g_qkv [(size_t)S_LEN * QKVD];
__device__ float g_sc  [(size_t)NH * S_LEN * S_LEN];
__device__ float g_tmp [(size_t)S_LEN * H_DIM];
__device__ float g_x1  [(size_t)S_LEN * H_DIM];
__device__ float g_gu  [(size_t)S_LEN * GUD];

#define TBUFA(name, R, K) __device__ __align__(16384) char name[(size_t)(R) * (K) * 4]
#define TBUFB(name, R, K) __device__ __align__(16384) char name[(size_t)(R) * (K) * 2]
TBUFB(c_wqkvt, QKVD, H_DIM);
TBUFB(c_wot,  H_DIM, NQD);
TBUFB(c_wgut, GUD,  H_DIM);
TBUFB(c_wdt,  H_DIM, I_DIM);
TBUFA(c_h,    S_LEN, H_DIM);
TBUFA(c_q,    S_LEN, NQD);
TBUFB(c_k,    S_LEN, NKVD);
TBUFB(c_vt,   NKVD, S_LEN);
TBUFA(c_p,    (size_t)NH * S_LEN, S_LEN);
TBUFA(c_at,   S_LEN, NQD);
TBUFA(c_gu,   S_LEN, I_DIM);

// ---------------------------------------------------------------------------
// helpers
// ---------------------------------------------------------------------------
__device__ __forceinline__ void hsplit(float x, __half& h, __half& l) {
    h = __float2half_rn(x);
    l = __float2half_rn(x - __half2float(h));
}
__device__ __forceinline__ uint32_t packh(__half a, __half b) {
    __half2 t(a, b);
    return *reinterpret_cast<uint32_t*>(&t);
}

template<bool IS_MAX>
__device__ __forceinline__ float block_reduce(float v) {
    __shared__ float sh[8];
    __syncthreads();
    int lane = threadIdx.x & 31, wid = threadIdx.x >> 5;
    #pragma unroll
    for (int o = 16; o; o >>= 1) {
        float t = __shfl_xor_sync(0xffffffffu, v, o);
        v = IS_MAX ? fmaxf(v, t) : (v + t);
    }
    if (lane == 0) sh[wid] = v;
    __syncthreads();
    if (wid == 0) {
        float r = (threadIdx.x < 8) ? sh[threadIdx.x] : (IS_MAX ? -3.4e38f : 0.0f);
        #pragma unroll
        for (int o = 4; o; o >>= 1) {
            float t = __shfl_xor_sync(0xffffffffu, r, o);
            r = IS_MAX ? fmaxf(r, t) : (r + t);
        }
        if (lane == 0) sh[0] = r;
    }
    __syncthreads();
    return sh[0];
}

__device__ __forceinline__ uint32_t smem_u32(const void* p) {
    uint32_t a;
    asm("{ .reg .u64 t; cvta.to.shared.u64 t, %1; cvt.u32.u64 %0, t; }" : "=r"(a) : "l"(p));
    return a;
}

#define MBAR_INIT(a, cnt) asm volatile("mbarrier.init.shared.b64 [%0], %1;" :: "r"(a), "r"(cnt) : "memory")
#define MBAR_EXPECT_TX(a, n) asm volatile("mbarrier.arrive.expect_tx.shared.b64 _, [%0], %1;" :: "r"(a), "r"(n) : "memory")
#define MBAR_WAIT(a, ph)  do {                                                               \
    asm volatile("{\n .reg .pred P1;\n"                                                      \
                 "WL%=:\n mbarrier.try_wait.parity.acquire.cta.shared::cta.b64 P1,[%0],%1,0x989680;\n" \
                 "@P1 bra.uni WD%=;\n bra.uni WL%=;\nWD%=:\n}"                               \
                 :: "r"(a), "r"(ph) : "memory"); } while (0)
#define BULK_G2S(dst, src, n, bar) \
    asm volatile("cp.async.bulk.shared::cluster.global.mbarrier::complete_tx::bytes [%0], [%1], %2, [%3];" \
                 :: "r"(dst), "l"(__cvta_generic_to_global(src)), "r"(n), "r"(bar) : "memory")

__device__ __forceinline__ void mma_f16(float* c, const uint32_t* a, const uint32_t* b) {
    asm volatile(
        "mma.sync.aligned.m16n8k16.row.col.f32.f16.f16.f32 "
        "{%0,%1,%2,%3}, {%4,%5,%6,%7}, {%8,%9}, {%0,%1,%2,%3};\n"
        : "+f"(c[0]), "+f"(c[1]), "+f"(c[2]), "+f"(c[3])
        : "r"(a[0]), "r"(a[1]), "r"(a[2]), "r"(a[3]), "r"(b[0]), "r"(b[1]));
}
__device__ __forceinline__ void ldsm4(uint32_t* r, uint32_t addr) {
    asm volatile("ldmatrix.sync.aligned.m8n8.x4.shared.b16 {%0,%1,%2,%3}, [%4];"
                 : "=r"(r[0]), "=r"(r[1]), "=r"(r[2]), "=r"(r[3]) : "r"(addr));
}

// ---------------------------------------------------------------------------
// mma.sync GEMM on pre-tiled fp16 operands:  C[M, N] = A[M, K] * B[N, K]^T
//   A = hi/lo 16KB tiles; B = hi-only 8KB tiles.
//   2-product emulation: acc += Ah*Bh + Al*Bh.
//   CTA tile 128x256x32, 8 warps (2M x 4N). Stage = A 16KB + 2x B 8KB = 32KB.
//   4-stage ring fed by cp.async.bulk + mbarrier tx (thread 0).
//   CMODE 0 plain; 1 causal skip; 2 K clip (brow*4+4 tiles).
//   OUT 0: fp32 row-major (+ bz*sC). OUT 1: A-side tiled fp16 (ldcT ktn).
// ---------------------------------------------------------------------------
#define STG_BYTES 32768
#define NSTG      4
#define GEMM_SMEM (1024 + NSTG * STG_BYTES)

template<int CMODE, int OUT>
__global__ void __launch_bounds__(256, 1)
gemm_mma(const char* __restrict__ At, const char* __restrict__ Bt,
         float* __restrict__ C, char* __restrict__ Ct,
         int nkTot, int ldaT, int ldbT, int ldcF, int ldcT, long long sC,
         long long sAT, long long sBT, int zdivB, int ccol)
{
    const int brow = blockIdx.x, bcol = blockIdx.y, bz = blockIdx.z;
    if (CMODE == 1 && 2 * bcol > brow) return;

    int nk = nkTot;
    if (CMODE == 2) nk = min(nkTot, brow * 4 + 4);

    const long long aBase = bz * sAT + (long long)brow * ldaT;
    const long long bT0 = (bz / zdivB) * sBT + (long long)(bcol * 2) * ldbT;
    const long long bT1 = bT0 + ldbT;

    extern __shared__ char smem[];
    const uint32_t smb = smem_u32(smem);

    const int tid  = threadIdx.x;
    const int lane = tid & 31;
    const int wid  = tid >> 5;
    const int warp_m = (wid & 1) * 64;
    const int warp_n = (wid >> 1) * 64;
    const uint32_t bbadd = 16384u + (uint32_t)(warp_n >> 7) * 8192u;

    if (tid == 0) {
        #pragma unroll
        for (int s = 0; s < NSTG; s++) MBAR_INIT(smb + 16 * s, 1);
    }
    asm volatile("fence.proxy.async.shared::cta;" ::: "memory");
    __syncthreads();

    // ---- fragment smem offsets (within a 4KB k16 plane) ----
    const int bsel = lane >> 3, jj = lane & 7;
    uint32_t aoff[4], boff[2][2];
    #pragma unroll
    for (int mi = 0; mi < 4; mi++) {
        const int r = warp_m + mi * 16 + (bsel & 1) * 8 + jj;
        const int c = bsel >> 1;
        aoff[mi] = r * 32 + ((c ^ ((r >> 2) & 1)) << 4);
    }
    #pragma unroll
    for (int ng = 0; ng < 2; ng++)
        #pragma unroll
        for (int q = 0; q < 2; q++) {
            const int r = (warp_n & 127) + ng * 32 + q * 16 + (bsel >> 1) * 8 + jj;
            const int c = bsel & 1;
            boff[ng][q] = r * 32 + ((c ^ ((r >> 2) & 1)) << 4);
        }

    auto fill = [&](int kt, int s) {   // thread 0 only
        const uint32_t bar = smb + 16 * s;
        const uint32_t sb = smb + 1024 + s * STG_BYTES;
        MBAR_EXPECT_TX(bar, (uint32_t)STG_BYTES);
        BULK_G2S(sb,          At + (aBase + kt) * 16384LL, 16384u, bar);
        BULK_G2S(sb + 16384u, Bt + (bT0 + kt) * 8192LL,    8192u,  bar);
        BULK_G2S(sb + 24576u, Bt + (bT1 + kt) * 8192LL,    8192u,  bar);
    };

    float acc[4][8][4];
    #pragma unroll
    for (int mi = 0; mi < 4; mi++)
        #pragma unroll
        for (int ni = 0; ni < 8; ni++)
            #pragma unroll
            for (int r = 0; r < 4; r++) acc[mi][ni][r] = 0.0f;

    auto compute_stage = [&](int s) {
        const uint32_t sb = smb + 1024 + s * STG_BYTES;
        #pragma unroll
        for (int h = 0; h < 2; h++) {
            const uint32_t aph = sb + h * 4096u;          // A hi plane
            const uint32_t apl = aph + 8192u;             // A lo plane
            const uint32_t bph = sb + bbadd + h * 4096u;  // B hi plane

            uint32_t ah[4][4], al[4][4];
            #pragma unroll
            for (int mi = 0; mi < 4; mi++) {
                ldsm4(ah[mi], aph + aoff[mi]);
                ldsm4(al[mi], apl + aoff[mi]);
            }
            #pragma unroll
            for (int ng = 0; ng < 2; ng++) {
                uint32_t bh[4][2];
                #pragma unroll
                for (int q = 0; q < 2; q++) {
                    uint32_t r[4];
                    ldsm4(r, bph + boff[ng][q]);
                    bh[2*q][0] = r[0]; bh[2*q][1] = r[1];
                    bh[2*q+1][0] = r[2]; bh[2*q+1][1] = r[3];
                }
                // product-major: acc reuse distance = 16 MMAs
                #pragma unroll
                for (int ni = 0; ni < 4; ni++)
                    #pragma unroll
                    for (int mi = 0; mi < 4; mi++)
                        mma_f16(acc[mi][ng*4+ni], ah[mi], bh[ni]);
                #pragma unroll
                for (int ni = 0; ni < 4; ni++)
                    #pragma unroll
                    for (int mi = 0; mi < 4; mi++)
                        mma_f16(acc[mi][ng*4+ni], al[mi], bh[ni]);
            }
        }
    };

    if (tid == 0) {
        for (int s = 0; s < NSTG && s < nk; s++) fill(s, s);
    }
    for (int kt = 0; kt < nk; kt++) {
        const int s = kt & (NSTG - 1);
        const int m = kt >> 2;
        MBAR_WAIT(smb + 16 * s, m & 1);
        compute_stage(s);
        __syncthreads();
        if (tid == 0 && kt + NSTG < nk) fill(kt + NSTG, s);
    }

    // ---- epilogue ----
    const int fr = lane >> 2, fc = (lane & 3) * 2;
    #pragma unroll
    for (int mi = 0; mi < 4; mi++) {
        const int row = brow * 128 + warp_m + mi * 16 + fr;
        #pragma unroll
        for (int ni = 0; ni < 8; ni++) {
            const int col = bcol * 256 + bz * ccol + warp_n + ni * 8 + fc;
            if (OUT == 0) {
                float* c0 = C + bz * sC + (long long)row * ldcF + col;
                float* c1 = C + bz * sC + (long long)(row + 8) * ldcF + col;
                *(float2*)c0 = make_float2(acc[mi][ni][0], acc[mi][ni][1]);
                *(float2*)c1 = make_float2(acc[mi][ni][2], acc[mi][ni][3]);
            } else {
                __half h0,l0,h1,l1,h2,l2,h3,l3;
                hsplit(acc[mi][ni][0], h0, l0); hsplit(acc[mi][ni][1], h1, l1);
                hsplit(acc[mi][ni][2], h2, l2); hsplit(acc[mi][ni][3], h3, l3);
                size_t o0 = tile_off(row, col, ldcT);
                size_t o1 = tile_off(row + 8, col, ldcT);
                *(uint32_t*)(Ct + o0)        = packh(h0, h1);
                *(uint32_t*)(Ct + o0 + 8192) = packh(l0, l1);
                *(uint32_t*)(Ct + o1)        = packh(h2, h3);
                *(uint32_t*)(Ct + o1 + 8192) = packh(l2, l3);
            }
        }
    }
}

// ---------------------------------------------------------------------------
// Transpose + tile (B-side, hi only): W[Kd, Nd] fp32 (stride ldw) -> T[Nd, Kd]
// ---------------------------------------------------------------------------
__global__ void tsplit_kernel(const float* __restrict__ W, char* __restrict__ T,
                              int Kd, int Nd, int ldw)
{
    __shared__ float t[32][33];
    const int n0 = blockIdx.x * 32, k0 = blockIdx.y * 32;
    const int tx = threadIdx.x, ty = threadIdx.y;
    const int ktn = Kd >> 5;
    #pragma unroll
    for (int i = 0; i < 4; i++)
        t[ty + i * 8][tx] = W[(long long)(k0 + ty + i * 8) * ldw + n0 + tx];
    __syncthreads();
    const int tid = ty * 32 + tx;
    if (tid < 128) {
        const int nn = tid >> 2, kq = (tid & 3) * 8;
        __half h[8];
        #pragma unroll
        for (int i = 0; i < 8; i++) h[i] = __float2half_rn(t[kq + i][nn]);
        const size_t off = tile_off8(n0 + nn, k0 + kq, ktn);
        *(uint4*)(T + off) = make_uint4(packh(h[0],h[1]), packh(h[2],h[3]),
                                        packh(h[4],h[5]), packh(h[6],h[7]));
    }
}

// ---------------------------------------------------------------------------
// RMSNorm -> A-side tiled hi/lo
// ---------------------------------------------------------------------------
__global__ void rmsnorm_split_kernel(const float* __restrict__ x,
                                     const float* __restrict__ w,
                                     char* __restrict__ out)
{
    const int row = blockIdx.x;
    const size_t base = (size_t)row * H_DIM;
    float ss = 0.0f;
    for (int j = threadIdx.x; j < H_DIM; j += blockDim.x) {
        float v = x[base + j]; ss += v * v;
    }
    ss = block_reduce<false>(ss);
    const float inv = rsqrtf(ss / (float)H_DIM + EPS_F);
    for (int ch = threadIdx.x; ch < H_DIM / 8; ch += blockDim.x) {
        const int k0 = ch * 8;
        const float4 a = *(const float4*)(x + base + k0);
        const float4 b = *(const float4*)(x + base + k0 + 4);
        const float4 wa = *(const float4*)(w + k0);
        const float4 wb = *(const float4*)(w + k0 + 4);
        const float vv[8] = { a.x*inv*wa.x, a.y*inv*wa.y, a.z*inv*wa.z, a.w*inv*wa.w,
                              b.x*inv*wb.x, b.y*inv*wb.y, b.z*inv*wb.z, b.w*inv*wb.w };
        __half h[8], l[8];
        #pragma unroll
        for (int i = 0; i < 8; i++) hsplit(vv[i], h[i], l[i]);
        const size_t off = tile_off(row, k0, H_DIM / 32);
        *(uint4*)(out + off) = make_uint4(packh(h[0],h[1]), packh(h[2],h[3]),
                                          packh(h[4],h[5]), packh(h[6],h[7]));
        *(uint4*)(out + off + 8192) = make_uint4(packh(l[0],l[1]), packh(l[2],l[3]),
                                                 packh(l[4],l[5]), packh(l[6],l[7]));
    }
}

__global__ void add_rmsnorm_kernel(const float* __restrict__ resid,
                                   const float* __restrict__ t,
                                   const float* __restrict__ w,
                                   float* __restrict__ out)
{
    const size_t base = (size_t)blockIdx.x * H_DIM;
    float ss = 0.0f;
    for (int j = threadIdx.x; j < H_DIM; j += blockDim.x) {
        float v = t[base + j]; ss += v * v;
    }
    ss = block_reduce<false>(ss);
    const float inv = rsqrtf(ss / (float)H_DIM + EPS_F);
    for (int j = threadIdx.x; j < H_DIM; j += blockDim.x)
        out[base + j] = resid[base + j] + t[base + j] * inv * w[j];
}

// ---------------------------------------------------------------------------
// RoPE -> Q A-side tiles (ktn=128), K B-side hi-only tiles (ktn=64)
// ---------------------------------------------------------------------------
__global__ void rope_split_kernel(const float* __restrict__ qkv,
                                  char* __restrict__ qt, char* __restrict__ kt)
{
    const int p = blockIdx.x;
    const int total = (NH + NKV) * 128;
    for (int t = threadIdx.x; t < total; t += blockDim.x) {
        const int d = t & 127;
        const float inv = powf(10000.0f, -(float)d * (1.0f / 128.0f));
        float sn, cs; sincosf((float)p * inv, &sn, &cs);
        if (t < NH * 128) {
            const int head = t >> 7;
            const size_t sbase = (size_t)p * QKVD + head * HD + d;
            const int col = head * HD + d;
            const float a = qkv[sbase], b = qkv[sbase + 128];
            __half h, l;
            size_t o = tile_off(p, col, NQD / 32);
            hsplit(a * cs - b * sn, h, l);
            *(__half*)(qt + o) = h; *(__half*)(qt + o + 8192) = l;
            o = tile_off(p, col + 128, NQD / 32);
            hsplit(b * cs + a * sn, h, l);
            *(__half*)(qt + o) = h; *(__half*)(qt + o + 8192) = l;
        } else {
            const int head = (t - NH * 128) >> 7;
            const size_t sbase = (size_t)p * QKVD + NQD + head * HD + d;
            const int col = head * HD + d;
            const float a = qkv[sbase], b = qkv[sbase + 128];
            *(__half*)(kt + tile_off8(p, col, NKVD / 32)) =
                __float2half_rn(a * cs - b * sn);
            *(__half*)(kt + tile_off8(p, col + 128, NKVD / 32)) =
                __float2half_rn(b * cs + a * sn);
        }
    }
}

// ---------------------------------------------------------------------------
// Softcap + causal softmax -> A-side tiled P per head; tail zeroed
// ---------------------------------------------------------------------------
__global__ void softmax_split_kernel(float* __restrict__ sc, char* __restrict__ pt)
{
    const int i = blockIdx.x, h = blockIdx.y;
    const size_t base = ((size_t)h * S_LEN + i) * S_LEN;
    float* row = sc + base;
    char* ph = pt + (size_t)h * ((S_LEN / 128) * (S_LEN / 32) * 16384);
    const int n = i + 1;

    float sm = 0.0f;
    for (int j = threadIdx.x; j < n; j += blockDim.x) {
        const float e = __expf(row[j] * (SCALE_F * 2.0f / SOFTCAP));
        const float cap = SOFTCAP * (1.0f - __fdividef(2.0f, e + 1.0f));
        const float p = __expf(cap);
        row[j] = p;
        sm += p;
    }
    sm = block_reduce<false>(sm);
    const float invs = 1.0f / sm;

    for (int j = threadIdx.x; j < n; j += blockDim.x) {
        __half hh, ll; hsplit(row[j] * invs, hh, ll);
        const size_t o = tile_off(i, j, S_LEN / 32);
        *(__half*)(ph + o) = hh; *(__half*)(ph + o + 8192) = ll;
    }
    const __half z = __float2half(0.0f);
    for (int j = n + threadIdx.x; j < S_LEN; j += blockDim.x) {
        const size_t o = tile_off(i, j, S_LEN / 32);
        *(__half*)(ph + o) = z; *(__half*)(ph + o + 8192) = z;
    }
}

// ---------------------------------------------------------------------------
// gelu_tanh(gate) * up -> A-side tiled hi/lo (ktn=448)
// ---------------------------------------------------------------------------
__global__ void gelumul_split_kernel(const float* __restrict__ gu, char* __restrict__ out)
{
    const int row = blockIdx.y;
    const int col = (blockIdx.x * blockDim.x + threadIdx.x) * 4;
    const float4 g4 = *(const float4*)(gu + (size_t)row * GUD + col);
    const float4 u4 = *(const float4*)(gu + (size_t)row * GUD + I_DIM + col);
    const float* gp = &g4.x; const float* up = &u4.x;
    __half h[4], l[4];
    #pragma unroll
    for (int t = 0; t < 4; t++) {
        const float xv = gp[t];
        const float inner = 0.7978845608028654f * (xv + 0.044715f * xv * xv * xv);
        const float r = 0.5f * xv * (1.0f + tanhf(inner)) * up[t];
        hsplit(r, h[t], l[t]);
    }
    const size_t off = tile_off(row, col, I_DIM / 32);
    *(uint2*)(out + off) = make_uint2(packh(h[0], h[1]), packh(h[2], h[3]));
    *(uint2*)(out + off + 8192) = make_uint2(packh(l[0], l[1]), packh(l[2], l[3]));
}

// ---------------------------------------------------------------------------
// Host launcher
// ---------------------------------------------------------------------------
#define SYM(v, s) do { cudaGetSymbolAddress((void**)&(v), s); } while (0)

extern "C" void kernel_launch(void* const* d_in, const int* in_sizes, int n_in,
                              void* d_out, int out_size)
{
    const float *x = nullptr, *w_in = nullptr, *w_pa = nullptr, *w_pf = nullptr,
                *w_pff = nullptr, *wq = nullptr, *wk = nullptr, *wv = nullptr,
                *wo = nullptr, *wg = nullptr, *wu = nullptr, *wd = nullptr;
    int c7 = 0, c14 = 0, c3584 = 0, c51 = 0;
    for (int i = 0; i < n_in; i++) {
        const int s = in_sizes[i];
        const float* p = (const float*)d_in[i];
        if (s == S_LEN * H_DIM) {
            if (c7 == 0) x = p; else if (c7 == 1) wk = p; else wv = p;
            c7++;
        } else if (s == H_DIM * NQD) {
            if (c14 == 0) wq = p; else wo = p;
            c14++;
        } else if (s == H_DIM) {
            if (c3584 == 0) w_in = p; else if (c3584 == 1) w_pa = p;
            else if (c3584 == 2) w_pf = p; else w_pff = p;
            c3584++;
        } else if (s == H_DIM * I_DIM) {
            if (c51 == 0) wg = p; else if (c51 == 1) wu = p; else wd = p;
            c51++;
        }
    }

    float *qkv_, *sc_, *tm_, *x1_, *gu_;
    SYM(qkv_, g_qkv); SYM(sc_, g_sc); SYM(tm_, g_tmp); SYM(x1_, g_x1); SYM(gu_, g_gu);
    char *wqkvt, *wot, *wgut, *wdt, *ht, *qt, *kt, *vt, *pt, *att, *gut;
    SYM(wqkvt, c_wqkvt); SYM(wot, c_wot); SYM(wgut, c_wgut); SYM(wdt, c_wdt);
    SYM(ht, c_h); SYM(qt, c_q); SYM(kt, c_k); SYM(vt, c_vt);
    SYM(pt, c_p); SYM(att, c_at); SYM(gut, c_gu);

    cudaFuncSetAttribute(gemm_mma<0,0>, cudaFuncAttributeMaxDynamicSharedMemorySize, GEMM_SMEM);
    cudaFuncSetAttribute(gemm_mma<1,0>, cudaFuncAttributeMaxDynamicSharedMemorySize, GEMM_SMEM);
    cudaFuncSetAttribute(gemm_mma<2,1>, cudaFuncAttributeMaxDynamicSharedMemorySize, GEMM_SMEM);

    const dim3 tb(32, 8);
    const long long SS = (long long)S_LEN * S_LEN;

    // ---- weight transpose + tile (hi only, 8KB tiles) ----
    tsplit_kernel<<<dim3(NQD/32,  H_DIM/32), tb>>>(wq, wqkvt, H_DIM, NQD, NQD);
    tsplit_kernel<<<dim3(NKVD/32, H_DIM/32), tb>>>(wk, wqkvt + (size_t)(NQD>>7)*112*8192,
                                                   H_DIM, NKVD, NKVD);
    tsplit_kernel<<<dim3(NKVD/32, H_DIM/32), tb>>>(wv, wqkvt + (size_t)((NQD+NKVD)>>7)*112*8192,
                                                   H_DIM, NKVD, NKVD);
    tsplit_kernel<<<dim3(H_DIM/32, NQD/32),  tb>>>(wo, wot, NQD, H_DIM, H_DIM);
    tsplit_kernel<<<dim3(I_DIM/32, H_DIM/32), tb>>>(wg, wgut, H_DIM, I_DIM, I_DIM);
    tsplit_kernel<<<dim3(I_DIM/32, H_DIM/32), tb>>>(wu, wgut + (size_t)(I_DIM>>7)*112*8192,
                                                    H_DIM, I_DIM, I_DIM);
    tsplit_kernel<<<dim3(H_DIM/32, I_DIM/32), tb>>>(wd, wdt, I_DIM, H_DIM, H_DIM);

    // 1) pre-attn norm
    rmsnorm_split_kernel<<<S_LEN, 256>>>(x, w_in, ht);

    // 2) fused QKV projection
    gemm_mma<0,0><<<dim3(16, QKVD/256, 1), 256, GEMM_SMEM>>>(
        ht, wqkvt, qkv_, nullptr, 112, 112, 112, QKVD, 0, 0, 0, 0, 1, 0);

    // 3) RoPE; V transpose
    rope_split_kernel<<<S_LEN, 256>>>(qkv_, qt, kt);
    tsplit_kernel<<<dim3(NKVD/32, S_LEN/32), tb>>>(qkv_ + NQD + NKVD, vt,
                                                   S_LEN, NKVD, QKVD);

    // 4) scores = Q K^T per head (causal tile skip); kv head = z/2
    gemm_mma<1,0><<<dim3(16, S_LEN/256, NH), 256, GEMM_SMEM>>>(
        qt, kt, sc_, nullptr, 8, 128, 64, S_LEN, 0, SS, 8, 8, 2, 0);

    // 5) softcap + softmax -> tiled P
    softmax_split_kernel<<<dim3(S_LEN, NH), 256>>>(sc_, pt);

    // 6) attn = P @ V^T per head (K clipped; tiled output); kv head = z/2
    gemm_mma<2,1><<<dim3(16, 1, NH), 256, GEMM_SMEM>>>(
        pt, vt, nullptr, att, 64, 64, 64, 0, 128, 0, 1024, 128, 2, 256);

    // 7) output projection
    gemm_mma<0,0><<<dim3(16, H_DIM/256, 1), 256, GEMM_SMEM>>>(
        att, wot, tm_, nullptr, 128, 128, 128, H_DIM, 0, 0, 0, 0, 1, 0);

    // 8) x1 = x + rms_norm(attn_out)
    add_rmsnorm_kernel<<<S_LEN, 256>>>(x, tm_, w_pa, x1_);

    // 9) pre-FF norm
    rmsnorm_split_kernel<<<S_LEN, 256>>>(x1_, w_pf, ht);

    // 10) fused gate|up projection
    gemm_mma<0,0><<<dim3(16, GUD/256, 1), 256, GEMM_SMEM>>>(
        ht, wgut, gu_, nullptr, 112, 112, 112, GUD, 0, 0, 0, 0, 1, 0);

    // 11) gelu_tanh(gate) * up
    gelumul_split_kernel<<<dim3(I_DIM/(256*4), S_LEN), 256>>>(gu_, gut);

    // 12) down projection
    gemm_mma<0,0><<<dim3(16, H_DIM/256, 1), 256, GEMM_SMEM>>>(
        gut, wdt, tm_, nullptr, 448, 448, 448, H_DIM, 0, 0, 0, 0, 1, 0);

    // 13) out = x1 + rms_norm(ff_out)
    add_rmsnorm_kernel<<<S_LEN, 256>>>(x1_, tm_, w_pff, (float*)d_out);

    (void)n_in; (void)out_size;
}